// round 16
// baseline (speedup 1.0000x reference)
#include <cuda_runtime.h>
#include <math.h>

// ChamferLoss_31044023616212: one-sided Chamfer distance
//   set1: [2, 8192, 3] f32, set2: [2, 8192, 3] f32 -> scalar f32
//
// R16: exact 2-D (z,y) cell pruning. z-only slabs failed (R13/R14): slab
// cost ~ slab_height x TOTAL density, but big radii occur in LOW density.
// A (z,y) rect scan costs ~ local density x area -> self-balancing.
//  * prep: bucket both sets into 96x96 (z,y) cells (row-contiguous), set2
//    stored pair-transposed for the packed FFMA2 scan; set1 keeps orig idx.
//  * search: warp = 32 cell-consecutive x points (local in z AND y).
//    phase A: scan own rect (+-1 y cell; expand until non-empty) -> exact
//    per-lane NN upper bound ub.  phase B: rect [wz +- r] x [wy +- r],
//    r = warp-max ub, covers every lane's ball B(x_i, ub_i) -> exact.
//    Rect rows are contiguous candidate ranges -> warp-uniform broadcast
//    packed scans (2 LDG.128 + 3 FFMA2 + 2 MIN per candidate pair).
//  * superset mins + orig-index writes + fixed-order final sum ->
//    deterministic, exact.  m = |y|^2 - 2<x,y> identity throughout.

#define NBATCH 2
#define NBZ    96
#define NBY    96
#define NCELL  (NBZ * NBY)
#define GMIN   (-6.0f)
#define GINV   8.0f                // 96 / 12
#define NMAX   8192
#define TS     128                 // 4 warps per search block

__device__ float  g_ypk[NBATCH][NMAX * 4];   // pair-transposed sorted set2
__device__ int    g_coff[NBATCH][NCELL + 1]; // cell start offsets (set2)
__device__ float4 g_x[NBATCH][NMAX];         // cell-sorted set1 (x,y,z,idx)
__device__ float  g_dist[NBATCH * NMAX];     // NN dist at original index
__device__ int    g_count = 0;

typedef unsigned long long u64;

__device__ __forceinline__ u64 ffma2(u64 a, u64 b, u64 c) {
    u64 d;
    asm("fma.rn.f32x2 %0, %1, %2, %3;" : "=l"(d) : "l"(a), "l"(b), "l"(c));
    return d;
}
__device__ __forceinline__ u64 bcast2(float x) {
    u64 r;
    asm("mov.b64 %0, {%1, %1};" : "=l"(r) : "f"(x));
    return r;
}
__device__ __forceinline__ void unpack2(u64 v, float& a, float& b) {
    asm("mov.b64 {%0, %1}, %2;" : "=f"(a), "=f"(b) : "l"(v));
}
__device__ __forceinline__ int binof(float v) {
    return min(max((int)((v - GMIN) * GINV), 0), NBZ - 1);
}

// ---------------- kernel 1: 2-D cell bucketing of both sets ----------------
extern "C" __global__ void __launch_bounds__(1024, 1)
bucket2d_kernel(const float* __restrict__ set1,
                const float* __restrict__ set2, int n)
{
    __shared__ int hist[NCELL];      // counts -> excl offsets -> cursors
    __shared__ int psum[1025];

    const int  job = blockIdx.x;     // 0,1: set2 b=0,1   2,3: set1 b=0,1
    const int  b   = job & 1;
    const bool isX = (job >> 1) != 0;
    const float* src = (isX ? set1 : set2) + (size_t)b * n * 3;
    const int tid = threadIdx.x;

    for (int i = tid; i < NCELL; i += 1024) hist[i] = 0;
    __syncthreads();

    for (int j = tid; j < n; j += 1024) {
        float y = src[3 * j + 1];
        float z = src[3 * j + 2];
        atomicAdd(&hist[binof(z) * NBY + binof(y)], 1);
    }
    __syncthreads();

    // ---- exclusive prefix over NCELL: 9 cells/thread + 1024-scan ----
    const int c0 = tid * (NCELL / 1024);          // 9 cells each
    int s = 0;
    #pragma unroll
    for (int k = 0; k < NCELL / 1024; ++k) s += hist[c0 + k];
    psum[tid + 1] = s;
    if (tid == 0) psum[0] = 0;
    __syncthreads();
    for (int st = 1; st < 1024; st <<= 1) {
        int add = 0;
        if (tid >= st) add = psum[tid + 1 - st];
        __syncthreads();
        psum[tid + 1] += add;
        __syncthreads();
    }
    {
        int run = psum[tid];
        #pragma unroll
        for (int k = 0; k < NCELL / 1024; ++k) {
            int t = hist[c0 + k];
            hist[c0 + k] = run;          // now exclusive offset
            run += t;
        }
    }
    __syncthreads();

    if (!isX) {
        for (int i = tid; i < NCELL; i += 1024) g_coff[b][i] = hist[i];
        if (tid == 0) g_coff[b][NCELL] = n;
    }
    __syncthreads();

    // ---- scatter (hist doubles as cursor) ----
    for (int j = tid; j < n; j += 1024) {
        float v0 = src[3 * j + 0];
        float v1 = src[3 * j + 1];
        float v2 = src[3 * j + 2];
        int cell = binof(v2) * NBY + binof(v1);
        int r = atomicAdd(&hist[cell], 1);
        if (isX) {
            g_x[b][r] = make_float4(v0, v1, v2, __int_as_float(j));
        } else {
            int pb = (r >> 1) * 8 + (r & 1);
            float* yp = g_ypk[b];
            yp[pb + 0] = -2.0f * v0;
            yp[pb + 2] = -2.0f * v1;
            yp[pb + 4] = -2.0f * v2;
            yp[pb + 6] = v0 * v0 + v1 * v1 + v2 * v2;
        }
    }
}

// warp-uniform packed scan of [r0, e0) rounded outward to pairs (superset)
__device__ __forceinline__ void scan_packed(const ulonglong2* __restrict__ Y2,
                                            int r0, int e0, int npairs,
                                            u64 X0, u64 X1, u64 X2,
                                            float& m0, float& m1)
{
    int plo = r0 >> 1;
    int phi = (e0 + 1) >> 1;
    if (phi > npairs) phi = npairs;
    int q = plo;
    for (; q + 1 < phi; q += 2) {
        ulonglong2 ua = Y2[2 * q],     va = Y2[2 * q + 1];
        ulonglong2 ub = Y2[2 * q + 2], vb = Y2[2 * q + 3];
        u64 ta = ffma2(X0, ua.x, ffma2(X1, ua.y, ffma2(X2, va.x, va.y)));
        u64 tb = ffma2(X0, ub.x, ffma2(X1, ub.y, ffma2(X2, vb.x, vb.y)));
        float al, ah, bl, bh;
        unpack2(ta, al, ah);
        unpack2(tb, bl, bh);
        m0 = fminf(m0, fminf(al, bl));
        m1 = fminf(m1, fminf(ah, bh));
    }
    if (q < phi) {
        ulonglong2 u = Y2[2 * q], v = Y2[2 * q + 1];
        u64 t = ffma2(X0, u.x, ffma2(X1, u.y, ffma2(X2, v.x, v.y)));
        float tl, th;
        unpack2(t, tl, th);
        m0 = fminf(m0, tl);
        m1 = fminf(m1, th);
    }
}

// ---------------- kernel 2: warp-rect coherent search ----------------
extern "C" __global__ void __launch_bounds__(TS, 1)
search_kernel(float* __restrict__ out, int n, int nblk)
{
    __shared__ int   scoff[NCELL + 1];
    __shared__ float buf[TS];
    __shared__ bool  amLast;

    const int tid  = threadIdx.x;
    const int w    = tid >> 5;
    const int lane = tid & 31;
    const int bx   = blockIdx.x;
    const int b    = blockIdx.y;

    for (int i = tid; i <= NCELL; i += TS) scoff[i] = g_coff[b][i];
    __syncthreads();

    const int pos = ((bx * (TS >> 5) + w) << 5) + lane;
    float4 X = g_x[b][pos];
    const float x0 = X.x, x1 = X.y, x2 = X.z;
    const int   orig = __float_as_int(X.w);
    const float sqx  = x0 * x0 + x1 * x1 + x2 * x2;
    const u64 X0 = bcast2(x0), X1 = bcast2(x1), X2 = bcast2(x2);

    const int myzb = binof(x2), myyb = binof(x1);

    // warp extents (bins and coords)
    int zbl = myzb, zbh = myzb, ybl = myyb, ybh = myyb;
    float wzl = x2, wzh = x2, wyl = x1, wyh = x1;
    #pragma unroll
    for (int o = 16; o > 0; o >>= 1) {
        zbl = min(zbl, __shfl_xor_sync(0xffffffffu, zbl, o));
        zbh = max(zbh, __shfl_xor_sync(0xffffffffu, zbh, o));
        ybl = min(ybl, __shfl_xor_sync(0xffffffffu, ybl, o));
        ybh = max(ybh, __shfl_xor_sync(0xffffffffu, ybh, o));
        wzl = fminf(wzl, __shfl_xor_sync(0xffffffffu, wzl, o));
        wzh = fmaxf(wzh, __shfl_xor_sync(0xffffffffu, wzh, o));
        wyl = fminf(wyl, __shfl_xor_sync(0xffffffffu, wyl, o));
        wyh = fmaxf(wyh, __shfl_xor_sync(0xffffffffu, wyh, o));
    }

    const ulonglong2* __restrict__ Y2 = (const ulonglong2*)g_ypk[b];
    const int npairs = n >> 1;

    // ---- phase A: own rect (+-1 y), expand until non-empty ----
    int za0 = zbl, za1 = zbh;
    int ya0 = max(ybl - 1, 0), ya1 = min(ybh + 1, NBY - 1);
    for (;;) {
        int cnt = 0;
        for (int zb = za0; zb <= za1; ++zb)
            cnt += scoff[zb * NBY + ya1 + 1] - scoff[zb * NBY + ya0];
        if (cnt > 0) break;
        bool grew = false;
        if (za0 > 0)       { --za0; grew = true; }
        if (za1 < NBZ - 1) { ++za1; grew = true; }
        if (ya0 > 0)       { --ya0; grew = true; }
        if (ya1 < NBY - 1) { ++ya1; grew = true; }
        if (!grew) break;
    }
    float m0 = 3.4e38f, m1 = 3.4e38f;
    for (int zb = za0; zb <= za1; ++zb)
        scan_packed(Y2, scoff[zb * NBY + ya0], scoff[zb * NBY + ya1 + 1],
                    npairs, X0, X1, X2, m0, m1);

    // per-lane exact upper bound, warp max -> rect radius
    float ub = sqrtf(fmaxf(fminf(m0, m1) + sqx, 0.0f));
    float rr = ub;
    #pragma unroll
    for (int o = 16; o > 0; o >>= 1)
        rr = fmaxf(rr, __shfl_xor_sync(0xffffffffu, rr, o));

    // ---- phase B: rect [wzl - rr, wzh + rr] x [wyl - rr, wyh + rr] ----
    const int zw0 = binof(wzl - rr), zw1 = binof(wzh + rr);
    const int yw0 = binof(wyl - rr), yw1 = binof(wyh + rr);
    for (int zb = zw0; zb <= zw1; ++zb)
        scan_packed(Y2, scoff[zb * NBY + yw0], scoff[zb * NBY + yw1 + 1],
                    npairs, X0, X1, X2, m0, m1);

    g_dist[b * n + orig] = sqrtf(fmaxf(fminf(m0, m1) + sqx, 0.0f));

    __threadfence();
    __syncthreads();
    if (tid == 0) amLast = (atomicAdd(&g_count, 1) == nblk - 1);
    __syncthreads();

    if (amLast) {
        float s = 0.0f;
        const int total = NBATCH * n;
        for (int i = tid; i < total; i += TS) s += __ldcg(&g_dist[i]);
        buf[tid] = s;
        __syncthreads();
        #pragma unroll
        for (int st = TS / 2; st > 0; st >>= 1) {
            if (tid < st) buf[tid] += buf[tid + st];
            __syncthreads();
        }
        if (tid == 0) {
            out[0]  = buf[0];
            g_count = 0;           // self-reset for graph replay
        }
    }
}

extern "C" void kernel_launch(void* const* d_in, const int* in_sizes, int n_in,
                              void* d_out, int out_size)
{
    const float* set1 = (const float*)d_in[0];
    const float* set2 = (const float*)d_in[1];

    // in_sizes[0] = b * n * d = 2 * n * 3
    const int n = in_sizes[0] / (NBATCH * 3);
    const int sbx  = n / TS;              // search blocks per batch (64)
    const int nblk = sbx * NBATCH;

    bucket2d_kernel<<<2 * NBATCH, 1024>>>(set1, set2, n);
    dim3 grid(sbx, NBATCH);
    search_kernel<<<grid, TS>>>((float*)d_out, n, nblk);
}

// round 17
// speedup vs baseline: 9.9103x; 9.9103x over previous
#include <cuda_runtime.h>
#include <math.h>

// ChamferLoss_31044023616212: one-sided Chamfer distance
//   set1: [2, 8192, 3] f32, set2: [2, 8192, 3] f32 -> scalar f32
//
// R17: brute force, SCALAR-FFMA inner loop. Evidence: R5/R6/R8 (all packed
// FFMA2 variants) were pinned at 36.9us with FFMA2 count the only invariant
// -> FFMA2 effective rt ~5.4 cyc (6-reg operand bank pressure). Scalar FFMA
// (3 scalar operands) runs at rt 2: total fma occupancy 42.5K cyc/SMSP vs
// 57.7K measured packed. Structure otherwise = validated R8 skeleton:
// T=1024 (8 warps/SMSP), 32 warp-uniform chunks over SMEM float4
// candidates (broadcast LDS.128), 4 x-points per thread, fused last-block
// deterministic reduction.
// m = |y|^2 - 2<x,y>;  d = sqrt(max(min m + |x|^2, 0))  (reference identity)

#define BPB      74            // blocks per batch; 74*2 = 148 blocks (1/SM)
#define NBATCH   2
#define T        1024
#define NCHUNK   32            // y-chunks, one per warp (chunk = warp id)
#define NSLOT    32            // x-slots (= lane id), 4 points each
#define RPAD     33            // rbuf row stride (32 chunks + pad)

__device__ float g_partials[BPB * NBATCH];
__device__ int   g_count = 0;

extern "C" __global__ void __launch_bounds__(T, 1)
chamfer_main_kernel(const float* __restrict__ set1,
                    const float* __restrict__ set2,
                    float* __restrict__ out,
                    int n)
{
    extern __shared__ float smem[];
    float4* s2  = (float4*)smem;                      // n candidates
    float* rbuf = smem + (size_t)n * 4;               // NSLOT*4*RPAD floats
    float* ssum = rbuf + NSLOT * 4 * RPAD;            // 32 floats

    const int tid = threadIdx.x;
    const int bx  = blockIdx.x;
    const int b   = blockIdx.y;

    // ---- cooperative preprocess of set2[b]: (-2y0, -2y1, -2y2, |y|^2) ----
    const float* p2 = set2 + (size_t)b * n * 3;
    for (int j = tid; j < n; j += T) {
        float y0 = p2[3 * j + 0];
        float y1 = p2[3 * j + 1];
        float y2 = p2[3 * j + 2];
        float sq = y0 * y0 + y1 * y1 + y2 * y2;
        s2[j] = make_float4(-2.0f * y0, -2.0f * y1, -2.0f * y2, sq);
    }
    __syncthreads();

    // ---- thread -> (x-slot = lane, y-chunk = warp): chunk warp-uniform ----
    const int w    = tid >> 5;     // 0..31 = chunk
    const int lane = tid & 31;     // 0..31 = slot

    // four set1 points per thread:  p = (lane + 32*pt)*BPB + bx  (iff p < n)
    const float* base1 = set1 + (size_t)b * n * 3;
    float x0[4], x1[4], x2[4];
    #pragma unroll
    for (int pt = 0; pt < 4; ++pt) {
        int p = (lane + (pt << 5)) * BPB + bx;
        float a0 = 0.f, a1 = 0.f, a2 = 0.f;
        if (p < n) {
            a0 = base1[3 * p + 0];
            a1 = base1[3 * p + 1];
            a2 = base1[3 * p + 2];
        }
        x0[pt] = a0; x1[pt] = a1; x2[pt] = a2;
    }

    const int QC = n / NCHUNK;     // 256 candidates per chunk
    const int j0 = w * QC;

    // ---- main loop: 2 LDS.128 + 24 FFMA + 8 FMNMX per 2 candidates ----
    float mn[4], mn2[4];
    #pragma unroll
    for (int pt = 0; pt < 4; ++pt) { mn[pt] = 3.4e38f; mn2[pt] = 3.4e38f; }

    #pragma unroll 4
    for (int j = j0; j < j0 + QC; j += 2) {
        float4 qa = s2[j];
        float4 qb = s2[j + 1];
        #pragma unroll
        for (int pt = 0; pt < 4; ++pt) {
            float ta = fmaf(x0[pt], qa.x,
                       fmaf(x1[pt], qa.y,
                       fmaf(x2[pt], qa.z, qa.w)));
            float tb = fmaf(x0[pt], qb.x,
                       fmaf(x1[pt], qb.y,
                       fmaf(x2[pt], qb.z, qb.w)));
            mn[pt]  = fminf(mn[pt],  ta);
            mn2[pt] = fminf(mn2[pt], tb);
        }
    }

    // ---- per (slot,pt) chunk-mins into padded rbuf ----
    #pragma unroll
    for (int pt = 0; pt < 4; ++pt)
        rbuf[(lane * 4 + pt) * RPAD + w] = fminf(mn[pt], mn2[pt]);
    __syncthreads();

    // ---- combine 32 chunks per point; threads 0..127 own one point each ----
    float dist = 0.0f;
    if (tid < NSLOT * 4) {
        const int slot = tid >> 2;
        const int pt   = tid & 3;
        float f = 3.4e38f;
        #pragma unroll
        for (int c = 0; c < NCHUNK; ++c)
            f = fminf(f, rbuf[(slot * 4 + pt) * RPAD + c]);
        const int p = (slot + (pt << 5)) * BPB + bx;
        if (p < n) {
            float a0 = base1[3 * p + 0];
            float a1 = base1[3 * p + 1];
            float a2 = base1[3 * p + 2];
            float sq = a0 * a0 + a1 * a1 + a2 * a2;
            dist = sqrtf(fmaxf(f + sq, 0.0f));
        }
        #pragma unroll
        for (int o = 16; o > 0; o >>= 1)
            dist += __shfl_xor_sync(0xffffffffu, dist, o);
        if (lane == 0) ssum[w] = dist;
    }
    __syncthreads();

    if (tid == 0) {
        float s = (ssum[0] + ssum[1]) + (ssum[2] + ssum[3]);
        g_partials[b * BPB + bx] = s;
        __threadfence();
        int t = atomicAdd(&g_count, 1);
        if (t == BPB * NBATCH - 1) {
            float tot = 0.0f;
            #pragma unroll 4
            for (int i = 0; i < BPB * NBATCH; ++i) tot += g_partials[i];
            out[0]  = tot;
            g_count = 0;    // self-reset for graph replay
        }
    }
}

extern "C" void kernel_launch(void* const* d_in, const int* in_sizes, int n_in,
                              void* d_out, int out_size)
{
    const float* set1 = (const float*)d_in[0];
    const float* set2 = (const float*)d_in[1];

    // in_sizes[0] = b * n * d = 2 * n * 3
    const int n = in_sizes[0] / (NBATCH * 3);

    const size_t smem = (size_t)n * 4 * sizeof(float)        // s2
                      + NSLOT * 4 * RPAD * sizeof(float)     // rbuf
                      + 32 * sizeof(float);                  // ssum
    cudaFuncSetAttribute(chamfer_main_kernel,
                         cudaFuncAttributeMaxDynamicSharedMemorySize, (int)smem);

    dim3 grid(BPB, NBATCH);
    chamfer_main_kernel<<<grid, T, smem>>>(set1, set2, (float*)d_out, n);
}